// round 10
// baseline (speedup 1.0000x reference)
#include <cuda_runtime.h>
#include <cuda_bf16.h>
#include <cstdint>

#define NBL 4096          // B*L
#define DK  256           // MMA-covered K extent (index 256 handled exactly in fp32)
#define OD  64

// ---------------- device scratch (no allocs allowed) ----------------
__device__ __align__(16) __nv_bfloat16 g_x1h[NBL*DK], g_x1l[NBL*DK];
__device__ __align__(16) __nv_bfloat16 g_x2h[NBL*DK], g_x2l[NBL*DK];
__device__ __align__(16) __nv_bfloat16 g_Uh[(size_t)OD*DK*DK], g_Ul[(size_t)OD*DK*DK];
__device__ __align__(16) __nv_bfloat16 g_Th[(size_t)NBL*OD*DK], g_Tl[(size_t)NBL*OD*DK];
__device__ float g_t256[NBL*OD];

// ---------------- helpers (baseline sm_90 ISA only: no tcgen05) ----------------
__device__ __forceinline__ uint32_t s2u(const void* p) {
    uint32_t a;
    asm("{ .reg .u64 t; cvta.to.shared.u64 t, %1; cvt.u32.u64 %0, t; }" : "=r"(a) : "l"(p));
    return a;
}
__device__ __forceinline__ void cp16(uint32_t s, const void* g) {
    asm volatile("cp.async.cg.shared.global [%0], [%1], 16;" :: "r"(s), "l"(g));
}
__device__ __forceinline__ void cp_commit() {
    asm volatile("cp.async.commit_group;");
}
template<int N> __device__ __forceinline__ void cp_wait() {
    asm volatile("cp.async.wait_group %0;" :: "n"(N));
}
__device__ __forceinline__ void ldsm4(uint32_t r[4], uint32_t addr) {
    asm volatile("ldmatrix.sync.aligned.m8n8.x4.shared.b16 {%0,%1,%2,%3}, [%4];"
        : "=r"(r[0]), "=r"(r[1]), "=r"(r[2]), "=r"(r[3]) : "r"(addr));
}
__device__ __forceinline__ void mma16(float c[4], const uint32_t a[4], uint32_t b0, uint32_t b1) {
    asm volatile("mma.sync.aligned.m16n8k16.row.col.f32.bf16.bf16.f32 "
        "{%0,%1,%2,%3}, {%4,%5,%6,%7}, {%8,%9}, {%0,%1,%2,%3};"
        : "+f"(c[0]), "+f"(c[1]), "+f"(c[2]), "+f"(c[3])
        : "r"(a[0]), "r"(a[1]), "r"(a[2]), "r"(a[3]), "r"(b0), "r"(b1));
}

// ---------------- preprocessing ----------------
__global__ __launch_bounds__(256) void x1split(const float* __restrict__ s) {
    int i = blockIdx.x * 256 + threadIdx.x;
    float x = s[i];
    __nv_bfloat16 h = __float2bfloat16(x);
    g_x1h[i] = h; g_x1l[i] = __float2bfloat16(x - __bfloat162float(h));
}
__global__ __launch_bounds__(256) void x2split(const float* __restrict__ s) {
    int i = blockIdx.x * 256 + threadIdx.x;
    float x = s[i];
    __nv_bfloat16 h = __float2bfloat16(x);
    g_x2h[i] = h; g_x2l[i] = __float2bfloat16(x - __bfloat162float(h));
}
__global__ __launch_bounds__(256) void usplit(const float* __restrict__ U) {
    size_t idx = (size_t)blockIdx.x * 256 + threadIdx.x;   // 64*256*256
    int o = (int)(idx >> 16), r = (int)(idx & 65535), i = r >> 8, j = r & 255;
    float x = U[((size_t)o * 257 + i) * 257 + j];
    __nv_bfloat16 h = __float2bfloat16(x);
    g_Uh[idx] = h; g_Ul[idx] = __float2bfloat16(x - __bfloat162float(h));
}

// t256[bl,o] = sum_j U[o,256,j]*x1a[bl,j] + U[o,256,256]  (exact fp32)
__global__ __launch_bounds__(256) void t256_k(const float* __restrict__ x1,
                                              const float* __restrict__ U) {
    extern __shared__ char sm[];
    float* Us  = (float*)sm;             // 64 x 261 (261%32=5 -> conflict-free)
    float* x1s = (float*)sm + 64 * 261;  // 4 x 256
    const int bl0 = blockIdx.x * 4, tid = threadIdx.x;

    for (int e = tid; e < 64 * 257; e += 256) {
        int o = e / 257, j = e - o * 257;
        Us[o * 261 + j] = U[((size_t)o * 257 + 256) * 257 + j];
    }
    for (int e = tid; e < 4 * 256; e += 256)
        x1s[e] = x1[(size_t)(bl0 + (e >> 8)) * 256 + (e & 255)];
    __syncthreads();

    const int blq = tid >> 6, o = tid & 63;
    const float* ur = Us + o * 261;
    const float* xr = x1s + blq * 256;
    float p[8];
    #pragma unroll
    for (int u = 0; u < 8; u++) p[u] = 0.f;
    #pragma unroll 4
    for (int j = 0; j < 256; j += 8)
        #pragma unroll
        for (int u = 0; u < 8; u++) p[u] = fmaf(xr[j + u], ur[j + u], p[u]);
    float acc = ur[256];
    #pragma unroll
    for (int u = 0; u < 8; u++) acc += p[u];
    g_t256[(size_t)(bl0 + blq) * 64 + o] = acc;
}

// ================= K1: CTA 128(bl) x 64(i), 3-stage pipeline, 1 sync/chunk ======
// stage (30720B): AH 10240 | AL 10240 | BH 5120 | BL 5120 ; rows padded to 80B
#define K1_ST0   512u
#define K1_STSZ  30720u
#define K1_SMEM  92672u   // 512 + 3*30720 -> 2 CTAs/SM

__device__ __forceinline__ void k1_copy(uint32_t st,
        const __nv_bfloat16* Ah, const __nv_bfloat16* Al,
        const __nv_bfloat16* Bh, const __nv_bfloat16* Bl, int k0) {
    const int tid = threadIdx.x;
    #pragma unroll
    for (int u = tid; u < 512; u += 256) {            // A: 128 rows x 4 16B-units
        int row = u >> 2, c = u & 3;
        uint32_t d = st + row * 80 + c * 16;
        const size_t go = (size_t)row * DK + k0 + c * 8;
        cp16(d, Ah + go);
        cp16(d + 10240u, Al + go);
    }
    {                                                  // B: 64 rows x 4 units = 256
        int row = tid >> 2, c = tid & 3;
        uint32_t d = st + 20480u + row * 80 + c * 16;
        const size_t go = (size_t)row * DK + k0 + c * 8;
        cp16(d, Bh + go);
        cp16(d + 5120u, Bl + go);
    }
    cp_commit();
}

__device__ __forceinline__ void k1_compute(uint32_t st, int lane, int wm, int wn,
                                           float c[2][4][4]) {
    uint32_t rowA = st + (uint32_t)((wm * 32 + (lane & 15)) * 80 + ((lane >> 4) * 16));
    uint32_t rowB = st + 20480u + (uint32_t)((wn * 32 + (lane & 15)) * 80 + ((lane >> 4) * 16));
    #pragma unroll
    for (int ks = 0; ks < 2; ks++) {
        uint32_t aH[2][4], aL[2][4], bH[2][4], bL[2][4];
        #pragma unroll
        for (int t = 0; t < 2; t++) {
            ldsm4(aH[t], rowA + t * 1280 + ks * 32);
            ldsm4(aL[t], rowA + 10240u + t * 1280 + ks * 32);
        }
        #pragma unroll
        for (int g = 0; g < 2; g++) {
            ldsm4(bH[g], rowB + g * 1280 + ks * 32);
            ldsm4(bL[g], rowB + 5120u + g * 1280 + ks * 32);
        }
        #pragma unroll
        for (int t = 0; t < 2; t++)
            #pragma unroll
            for (int g = 0; g < 2; g++)
                #pragma unroll
                for (int h = 0; h < 2; h++) {
                    float* acc = c[t][g * 2 + h];
                    mma16(acc, aH[t], bH[g][h], bH[g][h + 2]);   // hi*hi
                    mma16(acc, aH[t], bL[g][h], bL[g][h + 2]);   // hi*lo
                    mma16(acc, aL[t], bH[g][h], bH[g][h + 2]);   // lo*hi
                }
    }
}

__global__ __launch_bounds__(256, 2) void k1_mm(const float* __restrict__ U) {
    extern __shared__ char sm[];
    uint32_t sb = s2u(sm);
    const int tid = threadIdx.x, lane = tid & 31, wid = tid >> 5;
    const int wm = wid >> 1, wn = wid & 1;
    const int bl0 = blockIdx.x * 128, o = blockIdx.y, i0 = blockIdx.z * 64;

    float* ub = (float*)sm;   // bias col U[o, i0+n, 256]
    if (tid < 64) ub[tid] = U[((size_t)o * 257 + i0 + tid) * 257 + 256];

    const __nv_bfloat16* Ah = g_x1h + (size_t)bl0 * DK;
    const __nv_bfloat16* Al = g_x1l + (size_t)bl0 * DK;
    const __nv_bfloat16* Bh = g_Uh + (size_t)o * DK * DK + (size_t)i0 * DK;
    const __nv_bfloat16* Bl = g_Ul + (size_t)o * DK * DK + (size_t)i0 * DK;

    float c[2][4][4];
    #pragma unroll
    for (int t = 0; t < 2; t++)
        #pragma unroll
        for (int q = 0; q < 4; q++)
            #pragma unroll
            for (int e = 0; e < 4; e++) c[t][q][e] = 0.f;

    const uint32_t st[3] = { sb + K1_ST0, sb + K1_ST0 + K1_STSZ, sb + K1_ST0 + 2 * K1_STSZ };
    k1_copy(st[0], Ah, Al, Bh, Bl, 0);
    k1_copy(st[1], Ah, Al, Bh, Bl, 32);
    #pragma unroll 1
    for (int kc = 0; kc < 8; kc++) {
        if (kc == 7) cp_wait<0>(); else cp_wait<1>();
        __syncthreads();
        k1_compute(st[kc % 3], lane, wm, wn, c);
        if (kc < 6) k1_copy(st[(kc + 2) % 3], Ah, Al, Bh, Bl, (kc + 2) * 32);
    }

    const int mr = wm * 32 + (lane >> 2);
    const int nc = wn * 32 + (lane & 3) * 2;
    #pragma unroll
    for (int t = 0; t < 2; t++)
        #pragma unroll
        for (int q = 0; q < 4; q++) {
            int n = nc + q * 8;
            float b0f = ub[n], b1f = ub[n + 1];
            #pragma unroll
            for (int h = 0; h < 2; h++) {
                int m = bl0 + mr + t * 16 + h * 8;
                float v0 = c[t][q][h * 2 + 0] + b0f;
                float v1 = c[t][q][h * 2 + 1] + b1f;
                __nv_bfloat16 h0 = __float2bfloat16(v0);
                __nv_bfloat16 h1 = __float2bfloat16(v1);
                __nv_bfloat162 ph; ph.x = h0; ph.y = h1;
                __nv_bfloat162 pl;
                pl.x = __float2bfloat16(v0 - __bfloat162float(h0));
                pl.y = __float2bfloat16(v1 - __bfloat162float(h1));
                size_t base = ((size_t)m * OD + o) * DK + i0 + n;
                *reinterpret_cast<__nv_bfloat162*>(g_Th + base) = ph;
                *reinterpret_cast<__nv_bfloat162*>(g_Tl + base) = pl;
            }
        }
}

// ========== K2: persistent-B, 512 threads, 3-stage A pipeline, 1 sync/chunk ======
// smem: t2 256B | A stages s0/s1/s2 (each AH 20480 | AL 20480) | BH 64x528 | BL
#define K2_A0    256u
#define K2_ASZ   40960u
#define K2_B     123136u
#define K2_SMEM  190720u   // 1 CTA/SM

__device__ __forceinline__ void k2_copyA(uint32_t st,
        const __nv_bfloat16* Ah, const __nv_bfloat16* Al, int nx) {
    const int tid = threadIdx.x;
    const int mb2 = nx >> 3, k0 = (nx & 7) * 32;
    #pragma unroll
    for (int u = tid; u < 1024; u += 512) {   // 256 rows x 4 16B-units
        int row = u >> 2, c = u & 3;
        uint32_t d = st + row * 80 + c * 16;
        size_t go = (size_t)(mb2 * 256 + row) * DK + k0 + c * 8;
        cp16(d, Ah + go);
        cp16(d + 20480u, Al + go);
    }
    cp_commit();
}
__device__ __forceinline__ void k2_copyB(uint32_t bbase,
        const __nv_bfloat16* Bh, const __nv_bfloat16* Bl) {
    const int tid = threadIdx.x;
    #pragma unroll
    for (int u = tid; u < 2048; u += 512) {   // 64 rows x 32 16B-units
        int row = u >> 5, c = u & 31;
        uint32_t d = bbase + row * 528 + c * 16;
        size_t go = (size_t)row * DK + c * 8;
        cp16(d, Bh + go);
        cp16(d + 33792u, Bl + go);
    }
    cp_commit();
}

__device__ __forceinline__ void k2_compute(uint32_t st, uint32_t bb, int koffB,
                                           int lane, int wm, int wn, float c[2][4][4]) {
    uint32_t rowA = st + (uint32_t)((wm * 32 + (lane & 15)) * 80 + ((lane >> 4) * 16));
    uint32_t rowB = bb + (uint32_t)((wn * 32 + (lane & 15)) * 528 + ((lane >> 4) * 16) + koffB);
    #pragma unroll
    for (int ks = 0; ks < 2; ks++) {
        uint32_t aH[2][4], aL[2][4], bH[2][4], bL[2][4];
        #pragma unroll
        for (int t = 0; t < 2; t++) {
            ldsm4(aH[t], rowA + t * 1280 + ks * 32);
            ldsm4(aL[t], rowA + 20480u + t * 1280 + ks * 32);
        }
        #pragma unroll
        for (int g = 0; g < 2; g++) {
            ldsm4(bH[g], rowB + g * 8448 + ks * 32);          // 16 rows * 528B
            ldsm4(bL[g], rowB + 33792u + g * 8448 + ks * 32);
        }
        #pragma unroll
        for (int t = 0; t < 2; t++)
            #pragma unroll
            for (int g = 0; g < 2; g++)
                #pragma unroll
                for (int h = 0; h < 2; h++) {
                    float* acc = c[t][g * 2 + h];
                    mma16(acc, aH[t], bH[g][h], bH[g][h + 2]);
                    mma16(acc, aH[t], bL[g][h], bL[g][h + 2]);
                    mma16(acc, aL[t], bH[g][h], bH[g][h + 2]);
                }
    }
}

__global__ __launch_bounds__(512, 1) void k2_mm(float* __restrict__ out) {
    extern __shared__ char sm[];
    uint32_t sb = s2u(sm);
    const int tid = threadIdx.x, lane = tid & 31, wid = tid >> 5;
    const int wm = wid >> 1, wn = wid & 1;          // 8 x 2 warp grid: 256m x 64o
    const int bl = blockIdx.x, b = bl >> 9;

    float* t2 = (float*)sm;   // T[bl,o,256] broadcast (x2a[m,256]==1)
    if (tid < 64) t2[tid] = g_t256[(size_t)bl * OD + tid];

    const __nv_bfloat16* Ah = g_x2h + (size_t)(b * 512) * DK;
    const __nv_bfloat16* Al = g_x2l + (size_t)(b * 512) * DK;

    const uint32_t st[3] = { sb + K2_A0, sb + K2_A0 + K2_ASZ, sb + K2_A0 + 2 * K2_ASZ };
    k2_copyB(sb + K2_B, g_Th + (size_t)bl * OD * DK, g_Tl + (size_t)bl * OD * DK);
    k2_copyA(st[0], Ah, Al, 0);
    k2_copyA(st[1], Ah, Al, 1);

    const int mr = wm * 32 + (lane >> 2);
    const int nc = wn * 32 + (lane & 3) * 2;

    #pragma unroll 1
    for (int mb = 0; mb < 2; mb++) {
        float c[2][4][4];
        #pragma unroll
        for (int t = 0; t < 2; t++)
            #pragma unroll
            for (int q = 0; q < 4; q++)
                #pragma unroll
                for (int e = 0; e < 4; e++) c[t][q][e] = 0.f;

        #pragma unroll 1
        for (int kc = 0; kc < 8; kc++) {
            const int it = mb * 8 + kc;
            if (it == 15) cp_wait<0>(); else cp_wait<1>();
            __syncthreads();
            k2_compute(st[it % 3], sb + K2_B, kc * 64, lane, wm, wn, c);
            if (it < 14) k2_copyA(st[(it + 2) % 3], Ah, Al, it + 2);
        }

        #pragma unroll
        for (int t = 0; t < 2; t++)
            #pragma unroll
            for (int q = 0; q < 4; q++) {
                int n = nc + q * 8;
                float b0f = t2[n], b1f = t2[n + 1];
                #pragma unroll
                for (int h = 0; h < 2; h++) {
                    int m = mb * 256 + mr + t * 16 + h * 8;
                    float2 v;
                    v.x = c[t][q][h * 2 + 0] + b0f;
                    v.y = c[t][q][h * 2 + 1] + b1f;
                    *reinterpret_cast<float2*>(out + ((size_t)bl * 512 + m) * OD + n) = v;
                }
            }
    }
}

// ---------------- launch ----------------
extern "C" void kernel_launch(void* const* d_in, const int* in_sizes, int n_in,
                              void* d_out, int out_size) {
    const float* x1 = (const float*)d_in[0];   // (8,512,1,256)
    const float* x2 = (const float*)d_in[1];   // (8,1,512,256)
    const float* U  = (const float*)d_in[2];   // (64,257,257)
    float* out = (float*)d_out;                // (8,512,512,64)

    cudaFuncSetAttribute(t256_k, cudaFuncAttributeMaxDynamicSharedMemorySize, 70912);
    cudaFuncSetAttribute(k1_mm, cudaFuncAttributeMaxDynamicSharedMemorySize, (int)K1_SMEM);
    cudaFuncSetAttribute(k2_mm, cudaFuncAttributeMaxDynamicSharedMemorySize, (int)K2_SMEM);

    x1split<<<4096, 256>>>(x1);
    x2split<<<4096, 256>>>(x2);
    usplit<<<16384, 256>>>(U);
    t256_k<<<1024, 256, 70912>>>(x1, U);
    k1_mm<<<dim3(32, 64, 4), 256, K1_SMEM>>>(U);
    k2_mm<<<4096, 512, K2_SMEM>>>(out);
}

// round 11
// speedup vs baseline: 1.1212x; 1.1212x over previous
#include <cuda_runtime.h>
#include <cuda_bf16.h>
#include <cstdint>

#define NBL 4096          // B*L
#define DK  256           // MMA-covered K extent (index 256 handled exactly in fp32)
#define OD  64

// ---------------- device scratch (no allocs allowed) ----------------
__device__ __align__(16) __nv_bfloat16 g_x1h[NBL*DK], g_x1l[NBL*DK];
__device__ __align__(16) __nv_bfloat16 g_x2h[NBL*DK], g_x2l[NBL*DK];
__device__ __align__(16) __nv_bfloat16 g_Uh[(size_t)OD*DK*DK], g_Ul[(size_t)OD*DK*DK];
__device__ __align__(16) __nv_bfloat16 g_Th[(size_t)NBL*OD*DK], g_Tl[(size_t)NBL*OD*DK];
__device__ float g_t256[NBL*OD];

// ---------------- helpers (baseline sm_90 ISA only: no tcgen05) ----------------
__device__ __forceinline__ uint32_t s2u(const void* p) {
    uint32_t a;
    asm("{ .reg .u64 t; cvta.to.shared.u64 t, %1; cvt.u32.u64 %0, t; }" : "=r"(a) : "l"(p));
    return a;
}
__device__ __forceinline__ void cp16(uint32_t s, const void* g) {
    asm volatile("cp.async.cg.shared.global [%0], [%1], 16;" :: "r"(s), "l"(g));
}
__device__ __forceinline__ void cp_commit() {
    asm volatile("cp.async.commit_group;");
}
template<int N> __device__ __forceinline__ void cp_wait() {
    asm volatile("cp.async.wait_group %0;" :: "n"(N));
}
__device__ __forceinline__ void ldsm4(uint32_t r[4], uint32_t addr) {
    asm volatile("ldmatrix.sync.aligned.m8n8.x4.shared.b16 {%0,%1,%2,%3}, [%4];"
        : "=r"(r[0]), "=r"(r[1]), "=r"(r[2]), "=r"(r[3]) : "r"(addr));
}
__device__ __forceinline__ void mma16(float c[4], const uint32_t a[4], uint32_t b0, uint32_t b1) {
    asm volatile("mma.sync.aligned.m16n8k16.row.col.f32.bf16.bf16.f32 "
        "{%0,%1,%2,%3}, {%4,%5,%6,%7}, {%8,%9}, {%0,%1,%2,%3};"
        : "+f"(c[0]), "+f"(c[1]), "+f"(c[2]), "+f"(c[3])
        : "r"(a[0]), "r"(a[1]), "r"(a[2]), "r"(a[3]), "r"(b0), "r"(b1));
}

// ================= K1: per-chunk A+B buffers, 2-stage, 3 CTAs/SM =================
// rows padded to 80B (k=32 bf16 = 64B + 16B pad) -> conflict-free ldmatrix
#define AHOFF 0
#define ALOFF 10240u   // 128 rows * 80B
#define BHOFF 20480u
#define BLOFF 25600u   // + 64 rows * 80B
#define BUFSZ 30720u
#define SMEMB (256u + 2u*BUFSZ)   // 61,696 B -> 3 CTAs/SM

__device__ __forceinline__ void copy_chunk(uint32_t bufb,
        const __nv_bfloat16* Ah, const __nv_bfloat16* Al,
        const __nv_bfloat16* Bh, const __nv_bfloat16* Bl, int k0) {
    const int tid = threadIdx.x;
    #pragma unroll
    for (int u = tid; u < 512; u += 256) {            // A: 128 rows x 4 16B-units
        int row = u >> 2, c = u & 3;
        uint32_t d = bufb + row * 80 + c * 16;
        const size_t go = (size_t)row * DK + k0 + c * 8;
        cp16(d + AHOFF, Ah + go);
        cp16(d + ALOFF, Al + go);
    }
    {                                                  // B: 64 rows x 4 units = 256
        int row = tid >> 2, c = tid & 3;
        uint32_t d = bufb + row * 80 + c * 16;
        const size_t go = (size_t)row * DK + k0 + c * 8;
        cp16(d + BHOFF, Bh + go);
        cp16(d + BLOFF, Bl + go);
    }
    cp_commit();
}

__device__ __forceinline__ void compute_chunk(uint32_t bufb, int lane, int wm, int wn,
                                              float c[2][4][4]) {
    uint32_t rowA = bufb + AHOFF + (uint32_t)((wm * 32 + (lane & 15)) * 80 + ((lane >> 4) * 16));
    uint32_t rowB = bufb + BHOFF + (uint32_t)((wn * 32 + (lane & 15)) * 80 + ((lane >> 4) * 16));
    #pragma unroll
    for (int ks = 0; ks < 2; ks++) {
        uint32_t aH[2][4], aL[2][4], bH[2][4], bL[2][4];
        #pragma unroll
        for (int t = 0; t < 2; t++) {
            ldsm4(aH[t], rowA + t * 1280 + ks * 32);
            ldsm4(aL[t], rowA + (ALOFF - AHOFF) + t * 1280 + ks * 32);
        }
        #pragma unroll
        for (int g = 0; g < 2; g++) {
            ldsm4(bH[g], rowB + g * 1280 + ks * 32);
            ldsm4(bL[g], rowB + (BLOFF - BHOFF) + g * 1280 + ks * 32);
        }
        #pragma unroll
        for (int t = 0; t < 2; t++)
            #pragma unroll
            for (int g = 0; g < 2; g++)
                #pragma unroll
                for (int h = 0; h < 2; h++) {
                    float* acc = c[t][g * 2 + h];
                    mma16(acc, aH[t], bH[g][h], bH[g][h + 2]);   // hi*hi
                    mma16(acc, aH[t], bL[g][h], bL[g][h + 2]);   // hi*lo
                    mma16(acc, aL[t], bH[g][h], bH[g][h + 2]);   // lo*hi
                }
    }
}

__device__ __forceinline__ void run_gemm(uint32_t sb,
        const __nv_bfloat16* Ah, const __nv_bfloat16* Al,
        const __nv_bfloat16* Bh, const __nv_bfloat16* Bl,
        int lane, int wm, int wn, float c[2][4][4]) {
    #pragma unroll
    for (int t = 0; t < 2; t++)
        #pragma unroll
        for (int n = 0; n < 4; n++)
            #pragma unroll
            for (int e = 0; e < 4; e++) c[t][n][e] = 0.f;

    const uint32_t b0 = sb + 256, b1 = b0 + BUFSZ;
    copy_chunk(b0, Ah, Al, Bh, Bl, 0);
    #pragma unroll 1
    for (int kc = 0; kc < 8; kc++) {
        if (kc < 7) {
            copy_chunk(((kc + 1) & 1) ? b1 : b0, Ah, Al, Bh, Bl, (kc + 1) * 32);
            cp_wait<1>();
        } else {
            cp_wait<0>();
        }
        __syncthreads();
        compute_chunk((kc & 1) ? b1 : b0, lane, wm, wn, c);
        __syncthreads();
    }
}

// ---------------- preprocessing ----------------
// fused x1+x2 split: grid 8192, first half x1, second half x2
__global__ __launch_bounds__(256) void xsplit(const float* __restrict__ s1,
                                              const float* __restrict__ s2) {
    int i = (blockIdx.x & 4095) * 256 + threadIdx.x;
    if (blockIdx.x < 4096) {
        float x = s1[i];
        __nv_bfloat16 h = __float2bfloat16(x);
        g_x1h[i] = h; g_x1l[i] = __float2bfloat16(x - __bfloat162float(h));
    } else {
        float x = s2[i];
        __nv_bfloat16 h = __float2bfloat16(x);
        g_x2h[i] = h; g_x2l[i] = __float2bfloat16(x - __bfloat162float(h));
    }
}
__global__ __launch_bounds__(256) void usplit(const float* __restrict__ U) {
    size_t idx = (size_t)blockIdx.x * 256 + threadIdx.x;   // 64*256*256
    int o = (int)(idx >> 16), r = (int)(idx & 65535), i = r >> 8, j = r & 255;
    float x = U[((size_t)o * 257 + i) * 257 + j];
    __nv_bfloat16 h = __float2bfloat16(x);
    g_Uh[idx] = h; g_Ul[idx] = __float2bfloat16(x - __bfloat162float(h));
}

// t256[bl,o] = sum_j U[o,256,j]*x1a[bl,j] + U[o,256,256]  (exact fp32)
// 256 CTAs x 16 bl: U slice load amortized 4x vs R7; 4 outputs/thread.
__global__ __launch_bounds__(256) void t256_k(const float* __restrict__ x1,
                                              const float* __restrict__ U) {
    extern __shared__ char sm[];
    float* Us  = (float*)sm;              // 64 x 261 (261%32=5 -> conflict-free)
    float* x1s = (float*)sm + 64 * 261;   // 16 x 256
    const int bl0 = blockIdx.x * 16, tid = threadIdx.x;

    for (int e = tid; e < 64 * 257; e += 256) {
        int o = e / 257, j = e - o * 257;
        Us[o * 261 + j] = U[((size_t)o * 257 + 256) * 257 + j];
    }
    for (int e = tid; e < 16 * 256; e += 256)
        x1s[e] = x1[(size_t)(bl0 + (e >> 8)) * 256 + (e & 255)];
    __syncthreads();

    const int blq = tid >> 6, o = tid & 63;   // blq in 0..3; handles bl = blq*4 + v
    const float* ur = Us + o * 261;
    float acc[4];
    #pragma unroll
    for (int v = 0; v < 4; v++) acc[v] = ur[256];
    #pragma unroll 4
    for (int j = 0; j < 256; j++) {
        float u = ur[j];
        #pragma unroll
        for (int v = 0; v < 4; v++)
            acc[v] = fmaf(x1s[(blq * 4 + v) * 256 + j], u, acc[v]);
    }
    #pragma unroll
    for (int v = 0; v < 4; v++)
        g_t256[(size_t)(bl0 + blq * 4 + v) * 64 + o] = acc[v];
}

// ---------------- K1: T[bl,o,i] = sum_j U[o,i,j]*x1a[bl,j] ----------------
__global__ __launch_bounds__(256, 3) void k1_mm(const float* __restrict__ U) {
    extern __shared__ char sm[];
    uint32_t sb = s2u(sm);
    const int tid = threadIdx.x, lane = tid & 31, wid = tid >> 5;
    const int wm = wid >> 1, wn = wid & 1;
    const int bl0 = blockIdx.x * 128, o = blockIdx.y, i0 = blockIdx.z * 64;

    float* ub = (float*)sm;   // bias col U[o, i0+n, 256]
    if (tid < 64) ub[tid] = U[((size_t)o * 257 + i0 + tid) * 257 + 256];

    float c[2][4][4];
    run_gemm(sb,
             g_x1h + (size_t)bl0 * DK, g_x1l + (size_t)bl0 * DK,
             g_Uh + (size_t)o * DK * DK + (size_t)i0 * DK,
             g_Ul + (size_t)o * DK * DK + (size_t)i0 * DK,
             lane, wm, wn, c);

    const int mr = wm * 32 + (lane >> 2);
    const int nc = wn * 32 + (lane & 3) * 2;
    #pragma unroll
    for (int t = 0; t < 2; t++)
        #pragma unroll
        for (int n8 = 0; n8 < 4; n8++) {
            int n = nc + n8 * 8;
            float b0f = ub[n], b1f = ub[n + 1];
            #pragma unroll
            for (int h = 0; h < 2; h++) {
                int m = bl0 + mr + t * 16 + h * 8;
                float v0 = c[t][n8][h * 2 + 0] + b0f;
                float v1 = c[t][n8][h * 2 + 1] + b1f;
                __nv_bfloat16 h0 = __float2bfloat16(v0);
                __nv_bfloat16 h1 = __float2bfloat16(v1);
                __nv_bfloat162 ph; ph.x = h0; ph.y = h1;
                __nv_bfloat162 pl;
                pl.x = __float2bfloat16(v0 - __bfloat162float(h0));
                pl.y = __float2bfloat16(v1 - __bfloat162float(h1));
                size_t base = ((size_t)m * OD + o) * DK + i0 + n;
                *reinterpret_cast<__nv_bfloat162*>(g_Th + base) = ph;
                *reinterpret_cast<__nv_bfloat162*>(g_Tl + base) = pl;
            }
        }
}

// ================= K2: persistent-B, one CTA per bl, internal m-loop =================
// smem: [0,256) t2 | BH 64x528B | BL | A double buffers (chunk layout, 80B rows)
#define K2_BH   256u
#define K2_BL   34048u     // 256 + 64*528
#define K2_A0   67840u     // 256 + 2*33792
#define K2_A1   88320u     // + 20480
#define K2_SMEM 108800u    // -> 2 CTAs/SM

__device__ __forceinline__ void copy_B_full(uint32_t bbase,
        const __nv_bfloat16* Bh, const __nv_bfloat16* Bl) {
    const int tid = threadIdx.x;
    #pragma unroll
    for (int u = tid; u < 2048; u += 256) {   // 64 rows x 32 16B-units
        int row = u >> 5, c = u & 31;
        uint32_t d = bbase + row * 528 + c * 16;
        size_t go = (size_t)row * DK + c * 8;
        cp16(d, Bh + go);
        cp16(d + 33792u, Bl + go);
    }
}
__device__ __forceinline__ void copy_A_chunk(uint32_t bufb,
        const __nv_bfloat16* Ah, const __nv_bfloat16* Al, int k0) {
    const int tid = threadIdx.x;
    #pragma unroll
    for (int u = tid; u < 512; u += 256) {    // 128 rows x 4 16B-units
        int row = u >> 2, c = u & 3;
        uint32_t d = bufb + row * 80 + c * 16;
        size_t go = (size_t)row * DK + k0 + c * 8;
        cp16(d, Ah + go);
        cp16(d + 10240u, Al + go);
    }
}
__device__ __forceinline__ void compute_chunk_k2(uint32_t ab, uint32_t bb, int koffB,
                                                 int lane, int wm, int wn, float c[2][4][4]) {
    uint32_t rowA = ab + (uint32_t)((wm * 32 + (lane & 15)) * 80 + ((lane >> 4) * 16));
    uint32_t rowB = bb + (uint32_t)((wn * 32 + (lane & 15)) * 528 + ((lane >> 4) * 16) + koffB);
    #pragma unroll
    for (int ks = 0; ks < 2; ks++) {
        uint32_t aH[2][4], aL[2][4], bH[2][4], bL[2][4];
        #pragma unroll
        for (int t = 0; t < 2; t++) {
            ldsm4(aH[t], rowA + t * 1280 + ks * 32);
            ldsm4(aL[t], rowA + 10240u + t * 1280 + ks * 32);
        }
        #pragma unroll
        for (int g = 0; g < 2; g++) {
            ldsm4(bH[g], rowB + g * 8448 + ks * 32);          // 16 rows * 528B
            ldsm4(bL[g], rowB + 33792u + g * 8448 + ks * 32);
        }
        #pragma unroll
        for (int t = 0; t < 2; t++)
            #pragma unroll
            for (int g = 0; g < 2; g++)
                #pragma unroll
                for (int h = 0; h < 2; h++) {
                    float* acc = c[t][g * 2 + h];
                    mma16(acc, aH[t], bH[g][h], bH[g][h + 2]);
                    mma16(acc, aH[t], bL[g][h], bL[g][h + 2]);
                    mma16(acc, aL[t], bH[g][h], bH[g][h + 2]);
                }
    }
}

__global__ __launch_bounds__(256, 2) void k2_mm(float* __restrict__ out) {
    extern __shared__ char sm[];
    uint32_t sb = s2u(sm);
    const int tid = threadIdx.x, lane = tid & 31, wid = tid >> 5;
    const int wm = wid >> 1, wn = wid & 1;
    const int bl = blockIdx.x, b = bl >> 9;

    float* t2 = (float*)sm;   // T[bl,o,256] broadcast (x2a[m,256]==1)
    if (tid < 64) t2[tid] = g_t256[(size_t)bl * OD + tid];

    const __nv_bfloat16* Ahb = g_x2h + (size_t)(b * 512) * DK;
    const __nv_bfloat16* Alb = g_x2l + (size_t)(b * 512) * DK;

    copy_B_full(sb + K2_BH, g_Th + (size_t)bl * OD * DK, g_Tl + (size_t)bl * OD * DK);
    cp_commit();
    copy_A_chunk(sb + K2_A0, Ahb, Alb, 0);
    cp_commit();

    const uint32_t abuf[2] = { sb + K2_A0, sb + K2_A1 };
    const int mr = wm * 32 + (lane >> 2);
    const int nc = wn * 32 + (lane & 3) * 2;

    #pragma unroll 1
    for (int mb = 0; mb < 4; mb++) {
        float c[2][4][4];
        #pragma unroll
        for (int t = 0; t < 2; t++)
            #pragma unroll
            for (int n = 0; n < 4; n++)
                #pragma unroll
                for (int e = 0; e < 4; e++) c[t][n][e] = 0.f;

        #pragma unroll 1
        for (int kc = 0; kc < 8; kc++) {
            int it = mb * 8 + kc;
            if (it < 31) {
                int nx = it + 1, mb2 = nx >> 3, kc2 = nx & 7;
                copy_A_chunk(abuf[nx & 1], Ahb + (size_t)mb2 * 128 * DK,
                             Alb + (size_t)mb2 * 128 * DK, kc2 * 32);
                cp_commit();
                cp_wait<1>();
            } else {
                cp_wait<0>();
            }
            __syncthreads();
            compute_chunk_k2(abuf[it & 1], sb + K2_BH, kc * 64, lane, wm, wn, c);
            __syncthreads();
        }

        #pragma unroll
        for (int t = 0; t < 2; t++)
            #pragma unroll
            for (int n8 = 0; n8 < 4; n8++) {
                int n = nc + n8 * 8;
                float b0f = t2[n], b1f = t2[n + 1];
                #pragma unroll
                for (int h = 0; h < 2; h++) {
                    int m = mb * 128 + mr + t * 16 + h * 8;
                    float2 v;
                    v.x = c[t][n8][h * 2 + 0] + b0f;
                    v.y = c[t][n8][h * 2 + 1] + b1f;
                    *reinterpret_cast<float2*>(out + ((size_t)bl * 512 + m) * OD + n) = v;
                }
            }
    }
}

// ---------------- launch ----------------
extern "C" void kernel_launch(void* const* d_in, const int* in_sizes, int n_in,
                              void* d_out, int out_size) {
    const float* x1 = (const float*)d_in[0];   // (8,512,1,256)
    const float* x2 = (const float*)d_in[1];   // (8,1,512,256)
    const float* U  = (const float*)d_in[2];   // (64,257,257)
    float* out = (float*)d_out;                // (8,512,512,64)

    cudaFuncSetAttribute(t256_k, cudaFuncAttributeMaxDynamicSharedMemorySize, 83200);
    cudaFuncSetAttribute(k1_mm, cudaFuncAttributeMaxDynamicSharedMemorySize, (int)SMEMB);
    cudaFuncSetAttribute(k2_mm, cudaFuncAttributeMaxDynamicSharedMemorySize, (int)K2_SMEM);

    xsplit<<<8192, 256>>>(x1, x2);
    usplit<<<16384, 256>>>(U);
    t256_k<<<256, 256, 83200>>>(x1, U);
    k1_mm<<<dim3(32, 64, 4), 256, SMEMB>>>(U);
    k2_mm<<<4096, 256, K2_SMEM>>>(out);
}